// round 11
// baseline (speedup 1.0000x reference)
#include <cuda_runtime.h>
#include <cuda_bf16.h>
#include <cstdint>

// input_ids (64,1024) i32 | attention_mask (64,1024) i32 | hashed_vocab (768,30000) f32
// output (64,768) f32 = L2-normalized per-row minhash signatures.
// hv[h,v] = (a_h*v + b_h) mod P, P = 30011 = next_prime(30000).
//
// One fused kernel, 2 blocks per batch (grid=128, all co-resident), 768
// threads. Each block: builds the batch's valid-token byte map, then each
// warp recovers (a,b) and Fermat-inverts a for its OWN 16 hashes (lanes 0-15
// in parallel, one chain per warp, overlapped with the pre-probe barrier),
// distributes params by shuffle, and probes m=0,1,2,... via the inverse
// permutation (lane l checks m=32r+l, ballot -> min; 4 hashes in flight).
// Sibling blocks combine L2-norm partials via a self-resetting global
// atomic handshake.
#define BATCH 64
#define SEQ   1024
#define NH    768
#define HPB   384              // hashes per block
#define TPB   768
#define HPW   16               // hashes per warp (24 warps)
#define VOCAB 30000
#define PRIME 30011u
#define MAPB  30016            // byte map, padded to 16B multiple

__device__ float    g_sumsq[BATCH];   // zero-init at load; self-reset each call
__device__ unsigned g_count[BATCH];

__device__ __forceinline__ unsigned modmul(unsigned x, unsigned y) {
    return (x * y) % PRIME;    // products < 2^30; const mod -> mulhi magic
}

__global__ void __launch_bounds__(TPB, 1)
minhash_kernel(const int* __restrict__ ids,
               const int* __restrict__ mask,
               const float* __restrict__ hv,
               float* __restrict__ out)
{
    __shared__ uint4 pmap4[MAPB / 16];     // 30 KB byte map
    __shared__ float s_red[2];             // [0]=block partial, [1]=batch total

    const int b    = blockIdx.x >> 1;
    const int half = blockIdx.x & 1;
    const int t    = threadIdx.x;
    const int lane = t & 31;
    const int warp = t >> 5;               // 0..23
    const int wslot = warp * HPW;          // this warp's first hash (block-local)

    // ---- 0. front-load all global reads (latency hidden by map zeroing) ----
    int idA = ids [b * SEQ + t];
    int mkA = mask[b * SEQ + t];
    int idB = 0, mkB = 0;
    if (t < SEQ - TPB) {                   // threads 0..255 cover s = 768..1023
        idB = ids [b * SEQ + TPB + t];
        mkB = mask[b * SEQ + TPB + t];
    }
    float2 v01 = make_float2(0.f, 0.f);
    if (lane < HPW)                        // lane l owns hash wslot+l
        v01 = *reinterpret_cast<const float2*>(
                  hv + (size_t)(half * HPB + wslot + lane) * VOCAB);

    // ---- 1. zero map (STS.128) ----
    uint4 z = make_uint4(0u, 0u, 0u, 0u);
    #pragma unroll
    for (int i = t; i < MAPB / 16; i += TPB) pmap4[i] = z;
    if (t == 0) s_red[0] = 0.0f;
    __syncthreads();

    // ---- 2. scatter valid tokens ----
    unsigned char* present = reinterpret_cast<unsigned char*>(pmap4);
    if (mkA == 1 && idA > 100 && idA < VOCAB) present[idA] = 1;
    if (mkB == 1 && idB > 100 && idB < VOCAB) present[idB] = 1;

    // ---- 3. warp-local param recovery BEFORE the barrier (hides the chain)
    // lanes 0..15 each invert a for one hash; lanes 16..31 compute garbage
    // on zeros (harmless, keeps the warp convergent).
    unsigned bb = (unsigned)v01.x;
    unsigned aa = (unsigned)v01.y + PRIME - bb;
    if (aa >= PRIME) aa -= PRIME;
    unsigned ainv = 1u, base = aa;                 // a^(P-2) mod P (Fermat)
    #pragma unroll
    for (unsigned e = PRIME - 2u; e; e >>= 1u) {
        if (e & 1u) ainv = modmul(ainv, base);
        base = modmul(base, base);
    }
    unsigned id0v = modmul(ainv, (PRIME - bb) % PRIME);   // id at m=0
    __syncthreads();

    // ---- 4. probing: 16 hashes/warp, 4 chains in flight, params via shfl ----
    unsigned my_m = 0u;
    #pragma unroll 1
    for (int j = 0; j < HPW / 4; ++j) {
        unsigned idl[4], stp[4], res[4];
        bool fin[4];
        #pragma unroll
        for (int k = 0; k < 4; ++k) {
            unsigned av = __shfl_sync(0xffffffffu, ainv, j * 4 + k);
            unsigned i0 = __shfl_sync(0xffffffffu, id0v, j * 4 + k);
            unsigned v  = i0 + (unsigned)(lane * av) % PRIME;
            if (v >= PRIME) v -= PRIME;
            idl[k] = v;
            stp[k] = (av << 5) % PRIME;            // 32*ainv mod P
            fin[k] = false; res[k] = 0u;
        }
        unsigned mb = 0u;
        #pragma unroll 1
        for (;;) {
            bool alldone = true;
            #pragma unroll
            for (int k = 0; k < 4; ++k) {
                unsigned bal = __ballot_sync(0xffffffffu, present[idl[k]] != 0);
                if (!fin[k]) {
                    if (bal) { res[k] = mb + (unsigned)(__ffs(bal) - 1); fin[k] = true; }
                    else alldone = false;
                }
            }
            if (alldone) break;
            #pragma unroll
            for (int k = 0; k < 4; ++k) {
                idl[k] += stp[k];
                if (idl[k] >= PRIME) idl[k] -= PRIME;
            }
            mb += 32u;
            if (mb >= (unsigned)MAPB) break;       // unreachable with real data
        }
        #pragma unroll
        for (int k = 0; k < 4; ++k)
            if (lane == j * 4 + k) my_m = res[k];  // lanes 0..15 own results
    }

    // ---- 5. block partial of sum(m^2) ----
    float sv = (float)my_m;
    float part = (lane < HPW) ? sv * sv : 0.0f;
    #pragma unroll
    for (int o = 16; o > 0; o >>= 1)
        part += __shfl_xor_sync(0xffffffffu, part, o);
    if (lane == 0) atomicAdd(&s_red[0], part);
    __syncthreads();

    // ---- 6. sibling-block handshake (co-resident), self-resetting ----
    if (t == 0) {
        atomicAdd(&g_sumsq[b], s_red[0]);
        __threadfence();
        atomicAdd(&g_count[b], 1u);                // arrivals: 0->1->2
        while (atomicAdd(&g_count[b], 0u) < 2u) __nanosleep(32);
        __threadfence();
        s_red[1] = atomicAdd(&g_sumsq[b], 0.0f);   // batch total
        __threadfence();
        unsigned r = atomicAdd(&g_count[b], 1u);   // read-done: 2->3->4
        if (r == 3u) {                             // last reader resets
            atomicExch(&g_sumsq[b], 0.0f);
            atomicExch(&g_count[b], 0u);
        }
    }
    __syncthreads();

    float norm = sqrtf(s_red[1]);
    if (lane < HPW)
        out[b * NH + half * HPB + wslot + lane] = sv / fmaxf(norm, 1e-12f);
}

extern "C" void kernel_launch(void* const* d_in, const int* in_sizes, int n_in,
                              void* d_out, int out_size)
{
    const int*   ids  = (const int*)d_in[0];
    const int*   mask = (const int*)d_in[1];
    const float* hv   = (const float*)d_in[2];
    float*       out  = (float*)d_out;
    (void)in_sizes; (void)n_in; (void)out_size;

    minhash_kernel<<<BATCH * 2, TPB>>>(ids, mask, hv, out);
}